// round 1
// baseline (speedup 1.0000x reference)
#include <cuda_runtime.h>
#include <math.h>

// ---------------------------------------------------------------------------
// Problem dims
// ---------------------------------------------------------------------------
#define BB   8
#define SS   2048
#define DD   512
#define DKK  64
#define DFFN 2048
#define NREP 6
#define MSROWS (BB*SS)          // 16384
#define NTOT (BB*SS*DD)         // 8388608
#define RED_BLOCKS 2048

// ---------------------------------------------------------------------------
// Scratch (device globals; no runtime allocation allowed)
// ---------------------------------------------------------------------------
__device__ float g_x   [NTOT];
__device__ float g_x1  [NTOT];
__device__ float g_y   [NTOT];
__device__ float g_q   [MSROWS*DKK];
__device__ float g_k   [MSROWS*DKK];
__device__ float g_v   [MSROWS*DKK];
__device__ float g_head[MSROWS*DKK];
__device__ float g_scores[BB*SS*SS];        // 134 MB
__device__ float g_h   [MSROWS*DFFN];       // 134 MB
__device__ float g_woeff[DKK*DD];
__device__ float g_psum[RED_BLOCKS];
__device__ float g_psq [RED_BLOCKS];
__device__ float g_stats[2];                // mean, rstd

// ---------------------------------------------------------------------------
// Wo folding: concat = tile(head, 8) -> head @ Wo_eff, Wo_eff[t,e]=sum_j Wo[64j+t,e]
// ---------------------------------------------------------------------------
__global__ void woeff_kernel(const float* __restrict__ Wo) {
    int idx = blockIdx.x * blockDim.x + threadIdx.x;
    if (idx >= DKK * DD) return;
    int t = idx / DD, e = idx % DD;
    float s = 0.f;
#pragma unroll
    for (int j = 0; j < 8; j++) s += Wo[(j * DKK + t) * DD + e];
    g_woeff[idx] = s;
}

// ---------------------------------------------------------------------------
// Embedding + positional encoding:
//   x[b,s,d] = emb[ids[b,s], d]*(ids!=0) + (d even ? sin : cos)(s / 10000^(d/256))
// ---------------------------------------------------------------------------
__global__ void embed_kernel(const int* __restrict__ ids, const float* __restrict__ emb) {
    int i = blockIdx.x * blockDim.x + threadIdx.x;
    if (i >= NTOT) return;
    int d  = i & (DD - 1);
    int bs = i >> 9;            // /512
    int s  = bs & (SS - 1);
    int id = ids[bs];
    float v = (id != 0) ? emb[(long)id * DD + d] : 0.0f;
    double freq = pow(10000.0, (double)d / 256.0);
    float arg = (float)((double)s / freq);
    v += (d & 1) ? cosf(arg) : sinf(arg);
    g_x[i] = v;
}

// ---------------------------------------------------------------------------
// Register-blocked SGEMM.
//   C[M,N] = alpha * A[M,K] @ (TRB ? Bm[N,K]^T : Bm[K,N]) (+bias[n]) (+src[m,n]) (ReLU?)
//   All dims divide tiles exactly for every call site (checked statically below).
//   blockIdx.z = batch; per-batch strides are M*K / (N*K or K*N) / M*N.
// ---------------------------------------------------------------------------
template<int BM, int BN, int BK, int TM, int TN, bool TRB, bool RELU>
__global__ void __launch_bounds__(256)
gemm_kernel(const float* __restrict__ A, const float* __restrict__ Bm,
            const float* __restrict__ bias, const float* __restrict__ src,
            float* __restrict__ C, int M, int N, int K, float alpha)
{
    constexpr int TBN = BN / TN;
    static_assert((BM/TM)*(BN/TN) == 256, "256 threads");
    static_assert(BM*BK/4 == 256, "A load map");

    const int tid = threadIdx.x;
    const long bz = blockIdx.z;
    A  += bz * (long)M * K;
    Bm += bz * (TRB ? (long)N * K : (long)K * N);
    C  += bz * (long)M * N;
    const float* srcb = src ? src + bz * (long)M * N : (const float*)0;

    __shared__ float As[BK][BM];
    __shared__ float Bs[BK][BN];

    const int m0 = blockIdx.y * BM;
    const int n0 = blockIdx.x * BN;
    const int tr = tid / TBN;
    const int tc = tid % TBN;

    const int am = tid / (BK / 4);
    const int ak = (tid % (BK / 4)) * 4;

    float acc[TM][TN];
#pragma unroll
    for (int i = 0; i < TM; i++)
#pragma unroll
        for (int j = 0; j < TN; j++) acc[i][j] = 0.f;

    for (int k0 = 0; k0 < K; k0 += BK) {
        {   // A tile (transposed into smem)
            float4 a4 = *reinterpret_cast<const float4*>(&A[(long)(m0 + am) * K + k0 + ak]);
            As[ak + 0][am] = a4.x; As[ak + 1][am] = a4.y;
            As[ak + 2][am] = a4.z; As[ak + 3][am] = a4.w;
        }
        if (!TRB) {
            constexpr int NLD = BK * BN / 4;
            if (NLD == 256 || tid < NLD) {
                int bk = tid / (BN / 4);
                int bn = (tid % (BN / 4)) * 4;
                *reinterpret_cast<float4*>(&Bs[bk][bn]) =
                    *reinterpret_cast<const float4*>(&Bm[(long)(k0 + bk) * N + n0 + bn]);
            }
        } else {
            constexpr int NLD = BN * BK / 4;
            if (NLD == 256 || tid < NLD) {
                int bn = tid / (BK / 4);
                int bk = (tid % (BK / 4)) * 4;
                float4 b4 = *reinterpret_cast<const float4*>(&Bm[(long)(n0 + bn) * K + k0 + bk]);
                Bs[bk + 0][bn] = b4.x; Bs[bk + 1][bn] = b4.y;
                Bs[bk + 2][bn] = b4.z; Bs[bk + 3][bn] = b4.w;
            }
        }
        __syncthreads();
#pragma unroll
        for (int kk = 0; kk < BK; kk++) {
            float ra[TM], rb[TN];
#pragma unroll
            for (int i = 0; i < TM; i++) ra[i] = As[kk][tr * TM + i];
#pragma unroll
            for (int j = 0; j < TN; j++) rb[j] = Bs[kk][tc * TN + j];
#pragma unroll
            for (int i = 0; i < TM; i++)
#pragma unroll
                for (int j = 0; j < TN; j++)
                    acc[i][j] = fmaf(ra[i], rb[j], acc[i][j]);
        }
        __syncthreads();
    }

#pragma unroll
    for (int i = 0; i < TM; i++) {
        int m = m0 + tr * TM + i;
#pragma unroll
        for (int j = 0; j < TN; j++) {
            int n = n0 + tc * TN + j;
            float vv = acc[i][j] * alpha;
            if (bias) vv += bias[n];
            if (srcb) vv += srcb[(long)m * N + n];
            if (RELU) vv = fmaxf(vv, 0.f);
            C[(long)m * N + n] = vv;
        }
    }
}

// ---------------------------------------------------------------------------
// Row softmax over scores [B*S rows, S cols]; one block (256 thr) per row.
// ---------------------------------------------------------------------------
__global__ void softmax_kernel(float* __restrict__ sc) {
    long row = blockIdx.x;
    float* p = sc + row * (long)SS;
    __shared__ float red[256];
    int t = threadIdx.x;
    float vals[SS / 256];
    float mx = -1e30f;
#pragma unroll
    for (int j = 0; j < SS / 256; j++) {
        vals[j] = p[t + j * 256];
        mx = fmaxf(mx, vals[j]);
    }
    red[t] = mx; __syncthreads();
    for (int s = 128; s > 0; s >>= 1) {
        if (t < s) red[t] = fmaxf(red[t], red[t + s]);
        __syncthreads();
    }
    mx = red[0]; __syncthreads();
    float sum = 0.f;
#pragma unroll
    for (int j = 0; j < SS / 256; j++) {
        vals[j] = expf(vals[j] - mx);
        sum += vals[j];
    }
    red[t] = sum; __syncthreads();
    for (int s = 128; s > 0; s >>= 1) {
        if (t < s) red[t] += red[t + s];
        __syncthreads();
    }
    float inv = 1.0f / red[0];
#pragma unroll
    for (int j = 0; j < SS / 256; j++) p[t + j * 256] = vals[j] * inv;
}

// ---------------------------------------------------------------------------
// Whole-tensor LayerNorm (over all B*S*D elements), 3 stages.
// ---------------------------------------------------------------------------
__global__ void reduce_kernel(const float* __restrict__ y) {
    __shared__ float ssum[256], ssq[256];
    float a = 0.f, b = 0.f;
    for (int i = blockIdx.x * 256 + threadIdx.x; i < NTOT; i += RED_BLOCKS * 256) {
        float v = y[i];
        a += v; b += v * v;
    }
    ssum[threadIdx.x] = a; ssq[threadIdx.x] = b; __syncthreads();
    for (int s = 128; s > 0; s >>= 1) {
        if (threadIdx.x < s) {
            ssum[threadIdx.x] += ssum[threadIdx.x + s];
            ssq [threadIdx.x] += ssq [threadIdx.x + s];
        }
        __syncthreads();
    }
    if (threadIdx.x == 0) {
        g_psum[blockIdx.x] = ssum[0];
        g_psq [blockIdx.x] = ssq[0];
    }
}

__global__ void finalize_kernel() {
    __shared__ double ds[256], dq[256];
    double a = 0.0, b = 0.0;
    for (int i = threadIdx.x; i < RED_BLOCKS; i += 256) {
        a += (double)g_psum[i];
        b += (double)g_psq[i];
    }
    ds[threadIdx.x] = a; dq[threadIdx.x] = b; __syncthreads();
    for (int s = 128; s > 0; s >>= 1) {
        if (threadIdx.x < s) {
            ds[threadIdx.x] += ds[threadIdx.x + s];
            dq[threadIdx.x] += dq[threadIdx.x + s];
        }
        __syncthreads();
    }
    if (threadIdx.x == 0) {
        double m = ds[0] / (double)NTOT;
        double v = dq[0] / (double)NTOT - m * m;
        g_stats[0] = (float)m;
        g_stats[1] = (float)(1.0 / sqrt(v + 1e-5));
    }
}

__global__ void normalize_kernel(const float* __restrict__ y, float* __restrict__ out) {
    int i = blockIdx.x * blockDim.x + threadIdx.x;
    if (i < NTOT) out[i] = (y[i] - g_stats[0]) * g_stats[1];
}

// ---------------------------------------------------------------------------
// Launch
// ---------------------------------------------------------------------------
extern "C" void kernel_launch(void* const* d_in, const int* in_sizes, int n_in,
                              void* d_out, int out_size)
{
    const int*   ids = (const int*)  d_in[0];
    const float* emb = (const float*)d_in[1];
    const float* Wq  = (const float*)d_in[2];
    const float* bq  = (const float*)d_in[3];
    const float* Wk  = (const float*)d_in[4];
    const float* bk  = (const float*)d_in[5];
    const float* Wv  = (const float*)d_in[6];
    const float* bv  = (const float*)d_in[7];
    const float* Wo  = (const float*)d_in[8];
    const float* bo  = (const float*)d_in[9];
    const float* W1  = (const float*)d_in[10];
    const float* b1  = (const float*)d_in[11];
    const float* W2  = (const float*)d_in[12];
    const float* b2  = (const float*)d_in[13];

    float *x, *x1, *y, *q, *k, *v, *head, *scores, *h, *woeff;
    cudaGetSymbolAddress((void**)&x,      g_x);
    cudaGetSymbolAddress((void**)&x1,     g_x1);
    cudaGetSymbolAddress((void**)&y,      g_y);
    cudaGetSymbolAddress((void**)&q,      g_q);
    cudaGetSymbolAddress((void**)&k,      g_k);
    cudaGetSymbolAddress((void**)&v,      g_v);
    cudaGetSymbolAddress((void**)&head,   g_head);
    cudaGetSymbolAddress((void**)&scores, g_scores);
    cudaGetSymbolAddress((void**)&h,      g_h);
    cudaGetSymbolAddress((void**)&woeff,  g_woeff);

    const float inv_div = 1.0f / 32.0f;   // SCORE_DIV = (512/8)/2 = 32

    woeff_kernel<<<(DKK * DD + 255) / 256, 256>>>(Wo);
    embed_kernel<<<NTOT / 256, 256>>>(ids, emb);

    for (int it = 0; it < NREP; it++) {
        // Q, K, V:  [16384,512] @ [512,64]
        gemm_kernel<128, 64, 8, 8, 4, false, false>
            <<<dim3(1, MSROWS / 128, 1), 256>>>(x, Wq, bq, 0, q, MSROWS, DKK, DD, 1.f);
        gemm_kernel<128, 64, 8, 8, 4, false, false>
            <<<dim3(1, MSROWS / 128, 1), 256>>>(x, Wk, bk, 0, k, MSROWS, DKK, DD, 1.f);
        gemm_kernel<128, 64, 8, 8, 4, false, false>
            <<<dim3(1, MSROWS / 128, 1), 256>>>(x, Wv, bv, 0, v, MSROWS, DKK, DD, 1.f);

        // scores = q @ k^T / 32  (batched over B)
        gemm_kernel<128, 128, 8, 8, 8, true, false>
            <<<dim3(SS / 128, SS / 128, BB), 256>>>(q, k, 0, 0, scores, SS, SS, DKK, inv_div);

        softmax_kernel<<<BB * SS, 256>>>(scores);

        // head = attn @ v  (batched)
        gemm_kernel<128, 64, 8, 8, 4, false, false>
            <<<dim3(1, SS / 128, BB), 256>>>(scores, v, 0, 0, head, SS, DKK, SS, 1.f);

        // y = head @ Wo_eff + bo + x   (residual fused)
        gemm_kernel<128, 128, 8, 8, 8, false, false>
            <<<dim3(DD / 128, MSROWS / 128, 1), 256>>>(head, woeff, bo, x, y, MSROWS, DD, DKK, 1.f);

        // x1 = whole-tensor LN(y)
        reduce_kernel<<<RED_BLOCKS, 256>>>(y);
        finalize_kernel<<<1, 256>>>();
        normalize_kernel<<<NTOT / 256, 256>>>(y, x1);

        // h = relu(x1 @ W1 + b1)
        gemm_kernel<128, 128, 8, 8, 8, false, true>
            <<<dim3(DFFN / 128, MSROWS / 128, 1), 256>>>(x1, W1, b1, 0, h, MSROWS, DFFN, DD, 1.f);

        // y = h @ W2 + b2 + x1
        gemm_kernel<128, 128, 8, 8, 8, false, false>
            <<<dim3(DD / 128, MSROWS / 128, 1), 256>>>(h, W2, b2, x1, y, MSROWS, DD, DFFN, 1.f);

        // x = whole-tensor LN(y); final iteration writes straight to d_out
        reduce_kernel<<<RED_BLOCKS, 256>>>(y);
        finalize_kernel<<<1, 256>>>();
        float* dst = (it == NREP - 1) ? (float*)d_out : x;
        normalize_kernel<<<NTOT / 256, 256>>>(y, dst);
    }
}

// round 4
// speedup vs baseline: 1.9543x; 1.9543x over previous
#include <cuda_runtime.h>
#include <math.h>
#include <stdint.h>

// ---------------------------------------------------------------------------
// Problem dims
// ---------------------------------------------------------------------------
#define BB   8
#define SS   2048
#define DD   512
#define DKK  64
#define DFFN 2048
#define NREP 6
#define MSROWS (BB*SS)          // 16384
#define NTOT (BB*SS*DD)         // 8388608
#define RED_BLOCKS 2048

// ---------------------------------------------------------------------------
// Scratch (device globals; no runtime allocation allowed)
// ---------------------------------------------------------------------------
__device__ float g_x   [NTOT];
__device__ float g_x1  [NTOT];
__device__ float g_y   [NTOT];
__device__ float g_q   [MSROWS*DKK];
__device__ float g_k   [MSROWS*DKK];
__device__ float g_v   [MSROWS*DKK];
__device__ float g_vT  [BB*DKK*SS];
__device__ float g_head[MSROWS*DKK];
__device__ float g_scores[(long)BB*SS*SS]; // 134 MB
__device__ float g_h   [MSROWS*DFFN];      // 134 MB
__device__ float g_wqT [DKK*DD];
__device__ float g_wkT [DKK*DD];
__device__ float g_wvT [DKK*DD];
__device__ float g_w1T [DFFN*DD];
__device__ float g_w2T [DD*DFFN];
__device__ float g_woeffT[DD*DKK];
__device__ float g_psum[RED_BLOCKS];
__device__ float g_psq [RED_BLOCKS];
__device__ float g_stats[2];

// ---------------------------------------------------------------------------
// cp.async helpers (sm_80+, valid on plain sm_103 target)
// ---------------------------------------------------------------------------
__device__ __forceinline__ uint32_t cvta_shared_u32(const void* p) {
    uint32_t a;
    asm("{ .reg .u64 t; cvta.to.shared.u64 t, %1; cvt.u32.u64 %0, t; }" : "=r"(a) : "l"(p));
    return a;
}

__device__ __forceinline__ void cp_async16(uint32_t saddr, const void* gptr) {
    asm volatile("cp.async.cg.shared.global [%0], [%1], 16;" :: "r"(saddr), "l"(gptr));
}
__device__ __forceinline__ void cp_commit() {
    asm volatile("cp.async.commit_group;" ::: "memory");
}
template<int N>
__device__ __forceinline__ void cp_wait() {
    asm volatile("cp.async.wait_group %0;" :: "n"(N) : "memory");
}

// ---------------------------------------------------------------------------
// fp32 -> bf16 hi/lo split (packed bf16x2; element0 in low half)
// ---------------------------------------------------------------------------
__device__ __forceinline__ void split_bf16(float e0, float e1, uint32_t& hi, uint32_t& lo) {
    asm("cvt.rn.bf16x2.f32 %0, %1, %2;" : "=r"(hi) : "f"(e1), "f"(e0));
    float h0 = __uint_as_float(hi << 16);
    float h1 = __uint_as_float(hi & 0xffff0000u);
    float l0 = e0 - h0;
    float l1 = e1 - h1;
    asm("cvt.rn.bf16x2.f32 %0, %1, %2;" : "=r"(lo) : "f"(l1), "f"(l0));
}

__device__ __forceinline__ void mma_bf16(float* c, const uint32_t* a, const uint32_t* b) {
    asm volatile(
        "mma.sync.aligned.m16n8k16.row.col.f32.bf16.bf16.f32 "
        "{%0,%1,%2,%3}, {%4,%5,%6,%7}, {%8,%9}, {%0,%1,%2,%3};"
        : "+f"(c[0]), "+f"(c[1]), "+f"(c[2]), "+f"(c[3])
        : "r"(a[0]), "r"(a[1]), "r"(a[2]), "r"(a[3]), "r"(b[0]), "r"(b[1]));
}

// ---------------------------------------------------------------------------
// Split-bf16 mma.sync GEMM: C[M,N] = alpha * A[M,K] @ Bt[N,K]^T (+bias)(+src)(ReLU)
//   fp32-accurate via hi/lo bf16 decomposition (3 mma terms).
//   BM=128, BK=32 fixed. 256 threads = 8 warps, warp grid (128/WM) x (BN/WN).
//   Double-buffered smem via cp.async; padded stride 40 -> conflict-free LDS.64.
// ---------------------------------------------------------------------------
#define SMS 40   // smem row stride in floats (32 + 8 pad)

template<int BN, int WM, int WN, bool RELU>
__global__ void __launch_bounds__(256)
mma_gemm(const float* __restrict__ A, const float* __restrict__ Bt,
         const float* __restrict__ bias, const float* __restrict__ src,
         float* __restrict__ C, int M, int N, int K,
         long strideA, long strideB, long strideC, float alpha)
{
    constexpr int BM = 128;
    constexpr int MT = WM / 16;          // m16 tiles per warp
    constexpr int NT = WN / 8;           // n8 tiles per warp
    constexpr int WARPS_N = BN / WN;
    static_assert((BM / WM) * (BN / WN) == 8, "8 warps");

    extern __shared__ float smem[];
    constexpr int ASZ = BM * SMS;
    constexpr int BSZ = BN * SMS;
    float* As[2] = { smem,             smem + ASZ + BSZ };
    float* Bs[2] = { smem + ASZ,       smem + 2 * ASZ + BSZ };

    const int tid  = threadIdx.x;
    const int lane = tid & 31;
    const int wid  = tid >> 5;
    const int warp_m = wid / WARPS_N;
    const int warp_n = wid % WARPS_N;

    const long bz = blockIdx.z;
    A  += bz * strideA;
    Bt += bz * strideB;
    C  += bz * strideC;
    const float* srcp = src ? src + bz * strideC : (const float*)0;

    const int m0 = blockIdx.y * BM;
    const int n0 = blockIdx.x * BN;

    float acc[MT][NT][4];
#pragma unroll
    for (int i = 0; i < MT; i++)
#pragma unroll
        for (int j = 0; j < NT; j++)
#pragma unroll
            for (int u = 0; u < 4; u++) acc[i][j][u] = 0.f;

    const uint32_t sb = cvta_shared_u32(smem);
    const int nch = K >> 5;

    auto load_chunk = [&](int c, int buf) {
        const int k0 = c << 5;
        uint32_t abase = sb + (uint32_t)((buf ? ASZ + BSZ : 0)) * 4u;
        uint32_t bbase = sb + (uint32_t)((buf ? 2 * ASZ + BSZ : ASZ)) * 4u;
#pragma unroll
        for (int i = 0; i < (BM * 8) / 256; i++) {
            int idx = tid + i * 256;
            int row = idx >> 3, c4 = idx & 7;
            cp_async16(abase + (row * SMS + c4 * 4) * 4,
                       &A[(long)(m0 + row) * K + k0 + c4 * 4]);
        }
#pragma unroll
        for (int i = 0; i < (BN * 8) / 256; i++) {
            int idx = tid + i * 256;
            int row = idx >> 3, c4 = idx & 7;
            cp_async16(bbase + (row * SMS + c4 * 4) * 4,
                       &Bt[(long)(n0 + row) * K + k0 + c4 * 4]);
        }
    };

    load_chunk(0, 0);
    cp_commit();

    const int qr = lane >> 2;      // 0..7
    const int qc = lane & 3;       // 0..3

    for (int c = 0; c < nch; c++) {
        const int buf = c & 1;
        if (c + 1 < nch) {
            load_chunk(c + 1, buf ^ 1);
            cp_commit();
            cp_wait<1>();
        } else {
            cp_wait<0>();
        }
        __syncthreads();

        const float* Ab = As[buf];
        const float* Bb = Bs[buf];
#pragma unroll
        for (int ks = 0; ks < 2; ks++) {
            const int kk = ks * 16;
            uint32_t ah[MT][4], al[MT][4];
#pragma unroll
            for (int im = 0; im < MT; im++) {
                int r = warp_m * WM + im * 16 + qr;
                float2 p0 = *reinterpret_cast<const float2*>(&Ab[r * SMS + kk + 2 * qc]);
                float2 p1 = *reinterpret_cast<const float2*>(&Ab[(r + 8) * SMS + kk + 2 * qc]);
                float2 p2 = *reinterpret_cast<const float2*>(&Ab[r * SMS + kk + 8 + 2 * qc]);
                float2 p3 = *reinterpret_cast<const float2*>(&Ab[(r + 8) * SMS + kk + 8 + 2 * qc]);
                split_bf16(p0.x, p0.y, ah[im][0], al[im][0]);
                split_bf16(p1.x, p1.y, ah[im][1], al[im][1]);
                split_bf16(p2.x, p2.y, ah[im][2], al[im][2]);
                split_bf16(p3.x, p3.y, ah[im][3], al[im][3]);
            }
            uint32_t bh[NT][2], bl[NT][2];
#pragma unroll
            for (int in_ = 0; in_ < NT; in_++) {
                int n = warp_n * WN + in_ * 8 + qr;
                float2 q0 = *reinterpret_cast<const float2*>(&Bb[n * SMS + kk + 2 * qc]);
                float2 q1 = *reinterpret_cast<const float2*>(&Bb[n * SMS + kk + 8 + 2 * qc]);
                split_bf16(q0.x, q0.y, bh[in_][0], bl[in_][0]);
                split_bf16(q1.x, q1.y, bh[in_][1], bl[in_][1]);
            }
#pragma unroll
            for (int im = 0; im < MT; im++)
#pragma unroll
                for (int in_ = 0; in_ < NT; in_++) {
                    mma_bf16(acc[im][in_], ah[im], bh[in_]);
                    mma_bf16(acc[im][in_], al[im], bh[in_]);
                    mma_bf16(acc[im][in_], ah[im], bl[in_]);
                }
        }
        __syncthreads();
    }

    // ---- epilogue: c0,c1 -> (row, col..col+1); c2,c3 -> (row+8, ...) ----
#pragma unroll
    for (int im = 0; im < MT; im++) {
#pragma unroll
        for (int in_ = 0; in_ < NT; in_++) {
            int col = n0 + warp_n * WN + in_ * 8 + qc * 2;
            float b0 = 0.f, b1 = 0.f;
            if (bias) { b0 = bias[col]; b1 = bias[col + 1]; }
#pragma unroll
            for (int h = 0; h < 2; h++) {
                int row = m0 + warp_m * WM + im * 16 + qr + h * 8;
                float v0 = acc[im][in_][h * 2 + 0] * alpha + b0;
                float v1 = acc[im][in_][h * 2 + 1] * alpha + b1;
                if (srcp) {
                    const float2 s2 = *reinterpret_cast<const float2*>(&srcp[(long)row * N + col]);
                    v0 += s2.x; v1 += s2.y;
                }
                if (RELU) { v0 = fmaxf(v0, 0.f); v1 = fmaxf(v1, 0.f); }
                float2 o; o.x = v0; o.y = v1;
                *reinterpret_cast<float2*>(&C[(long)row * N + col]) = o;
            }
        }
    }
}

// ---------------------------------------------------------------------------
// Transpose: out[c*R + r] = in[r*C + c], batched over blockIdx.z (stride R*C)
// ---------------------------------------------------------------------------
__global__ void transpose_kernel(const float* __restrict__ in, float* __restrict__ out,
                                 int R, int C_) {
    __shared__ float t[32][33];
    long boff = (long)blockIdx.z * R * C_;
    int r0 = blockIdx.y * 32, c0 = blockIdx.x * 32;
#pragma unroll
    for (int i = 0; i < 32; i += 8) {
        int r = r0 + threadIdx.y + i, c = c0 + threadIdx.x;
        if (r < R && c < C_) t[threadIdx.y + i][threadIdx.x] = in[boff + (long)r * C_ + c];
    }
    __syncthreads();
#pragma unroll
    for (int i = 0; i < 32; i += 8) {
        int rr = c0 + threadIdx.y + i, cc = r0 + threadIdx.x;
        if (rr < C_ && cc < R) out[boff + (long)rr * R + cc] = t[threadIdx.x][threadIdx.y + i];
    }
}

// Wo_eff^T: out[e*64+t] = sum_j Wo[(j*64+t)*512 + e]   (shape [512,64])
__global__ void woeffT_kernel(const float* __restrict__ Wo) {
    int idx = blockIdx.x * blockDim.x + threadIdx.x;
    if (idx >= DD * DKK) return;
    int e = idx / DKK, t = idx % DKK;
    float s = 0.f;
#pragma unroll
    for (int j = 0; j < 8; j++) s += Wo[(j * DKK + t) * DD + e];
    g_woeffT[idx] = s;
}

// ---------------------------------------------------------------------------
// Embedding + positional encoding
// ---------------------------------------------------------------------------
__global__ void embed_kernel(const int* __restrict__ ids, const float* __restrict__ emb) {
    int i = blockIdx.x * blockDim.x + threadIdx.x;
    if (i >= NTOT) return;
    int d  = i & (DD - 1);
    int bs = i >> 9;
    int s  = bs & (SS - 1);
    int id = ids[bs];
    float v = (id != 0) ? emb[(long)id * DD + d] : 0.0f;
    double freq = pow(10000.0, (double)d / 256.0);
    float arg = (float)((double)s / freq);
    v += (d & 1) ? cosf(arg) : sinf(arg);
    g_x[i] = v;
}

// ---------------------------------------------------------------------------
// Row softmax over scores [B*S rows, S cols]
// ---------------------------------------------------------------------------
__global__ void softmax_kernel(float* __restrict__ sc) {
    long row = blockIdx.x;
    float* p = sc + row * (long)SS;
    __shared__ float red[256];
    int t = threadIdx.x;
    float vals[SS / 256];
    float mx = -1e30f;
#pragma unroll
    for (int j = 0; j < SS / 256; j++) {
        vals[j] = p[t + j * 256];
        mx = fmaxf(mx, vals[j]);
    }
    red[t] = mx; __syncthreads();
    for (int s = 128; s > 0; s >>= 1) {
        if (t < s) red[t] = fmaxf(red[t], red[t + s]);
        __syncthreads();
    }
    mx = red[0]; __syncthreads();
    float sum = 0.f;
#pragma unroll
    for (int j = 0; j < SS / 256; j++) {
        vals[j] = expf(vals[j] - mx);
        sum += vals[j];
    }
    red[t] = sum; __syncthreads();
    for (int s = 128; s > 0; s >>= 1) {
        if (t < s) red[t] += red[t + s];
        __syncthreads();
    }
    float inv = 1.0f / red[0];
#pragma unroll
    for (int j = 0; j < SS / 256; j++) p[t + j * 256] = vals[j] * inv;
}

// ---------------------------------------------------------------------------
// Whole-tensor LayerNorm, 3 stages
// ---------------------------------------------------------------------------
__global__ void reduce_kernel(const float* __restrict__ y) {
    __shared__ float ssum[256], ssq[256];
    float a = 0.f, b = 0.f;
    for (int i = blockIdx.x * 256 + threadIdx.x; i < NTOT; i += RED_BLOCKS * 256) {
        float v = y[i];
        a += v; b += v * v;
    }
    ssum[threadIdx.x] = a; ssq[threadIdx.x] = b; __syncthreads();
    for (int s = 128; s > 0; s >>= 1) {
        if (threadIdx.x < s) {
            ssum[threadIdx.x] += ssum[threadIdx.x + s];
            ssq [threadIdx.x] += ssq [threadIdx.x + s];
        }
        __syncthreads();
    }
    if (threadIdx.x == 0) { g_psum[blockIdx.x] = ssum[0]; g_psq[blockIdx.x] = ssq[0]; }
}

__global__ void finalize_kernel() {
    __shared__ double ds[256], dq[256];
    double a = 0.0, b = 0.0;
    for (int i = threadIdx.x; i < RED_BLOCKS; i += 256) {
        a += (double)g_psum[i];
        b += (double)g_psq[i];
    }
    ds[threadIdx.x] = a; dq[threadIdx.x] = b; __syncthreads();
    for (int s = 128; s > 0; s >>= 1) {
        if (threadIdx.x < s) {
            ds[threadIdx.x] += ds[threadIdx.x + s];
            dq[threadIdx.x] += dq[threadIdx.x + s];
        }
        __syncthreads();
    }
    if (threadIdx.x == 0) {
        double m = ds[0] / (double)NTOT;
        double v = dq[0] / (double)NTOT - m * m;
        g_stats[0] = (float)m;
        g_stats[1] = (float)(1.0 / sqrt(v + 1e-5));
    }
}

__global__ void normalize_kernel(const float* __restrict__ y, float* __restrict__ out) {
    int i = blockIdx.x * blockDim.x + threadIdx.x;
    if (i < NTOT) out[i] = (y[i] - g_stats[0]) * g_stats[1];
}

// ---------------------------------------------------------------------------
// Launch
// ---------------------------------------------------------------------------
extern "C" void kernel_launch(void* const* d_in, const int* in_sizes, int n_in,
                              void* d_out, int out_size)
{
    const int*   ids = (const int*)  d_in[0];
    const float* emb = (const float*)d_in[1];
    const float* Wq  = (const float*)d_in[2];
    const float* bq  = (const float*)d_in[3];
    const float* Wk  = (const float*)d_in[4];
    const float* bk  = (const float*)d_in[5];
    const float* Wv  = (const float*)d_in[6];
    const float* bv  = (const float*)d_in[7];
    const float* Wo  = (const float*)d_in[8];
    const float* bo  = (const float*)d_in[9];
    const float* W1  = (const float*)d_in[10];
    const float* b1  = (const float*)d_in[11];
    const float* W2  = (const float*)d_in[12];
    const float* b2  = (const float*)d_in[13];

    float *x, *x1, *y, *q, *k, *v, *vT, *head, *scores, *h;
    float *wqT, *wkT, *wvT, *w1T, *w2T, *woT;
    cudaGetSymbolAddress((void**)&x,      g_x);
    cudaGetSymbolAddress((void**)&x1,     g_x1);
    cudaGetSymbolAddress((void**)&y,      g_y);
    cudaGetSymbolAddress((void**)&q,      g_q);
    cudaGetSymbolAddress((void**)&k,      g_k);
    cudaGetSymbolAddress((void**)&v,      g_v);
    cudaGetSymbolAddress((void**)&vT,     g_vT);
    cudaGetSymbolAddress((void**)&head,   g_head);
    cudaGetSymbolAddress((void**)&scores, g_scores);
    cudaGetSymbolAddress((void**)&h,      g_h);
    cudaGetSymbolAddress((void**)&wqT,    g_wqT);
    cudaGetSymbolAddress((void**)&wkT,    g_wkT);
    cudaGetSymbolAddress((void**)&wvT,    g_wvT);
    cudaGetSymbolAddress((void**)&w1T,    g_w1T);
    cudaGetSymbolAddress((void**)&w2T,    g_w2T);
    cudaGetSymbolAddress((void**)&woT,    g_woeffT);

    // dynamic smem sizes: (A + B) rows * SMS floats * 2 buffers * 4B
    const int SM128 = (128 * SMS + 128 * SMS) * 2 * 4;  // 81920
    const int SM64  = (128 * SMS + 64  * SMS) * 2 * 4;  // 61440
    cudaFuncSetAttribute((const void*)mma_gemm<128, 64, 32, false>,
                         cudaFuncAttributeMaxDynamicSharedMemorySize, SM128);
    cudaFuncSetAttribute((const void*)mma_gemm<128, 64, 32, true>,
                         cudaFuncAttributeMaxDynamicSharedMemorySize, SM128);
    cudaFuncSetAttribute((const void*)mma_gemm<64, 64, 16, false>,
                         cudaFuncAttributeMaxDynamicSharedMemorySize, SM64);

    const float inv_div = 1.0f / 32.0f;
    dim3 tb(32, 8);

    // Weight prep (once per launch)
    transpose_kernel<<<dim3(2, 16, 1), tb>>>(Wq, wqT, DD, DKK);
    transpose_kernel<<<dim3(2, 16, 1), tb>>>(Wk, wkT, DD, DKK);
    transpose_kernel<<<dim3(2, 16, 1), tb>>>(Wv, wvT, DD, DKK);
    transpose_kernel<<<dim3(64, 16, 1), tb>>>(W1, w1T, DD, DFFN);
    transpose_kernel<<<dim3(16, 64, 1), tb>>>(W2, w2T, DFFN, DD);
    woeffT_kernel<<<(DD * DKK + 255) / 256, 256>>>(Wo);

    embed_kernel<<<NTOT / 256, 256>>>(ids, emb);

    for (int it = 0; it < NREP; it++) {
        // Q, K, V:  [16384,512] @ [512,64]^T(K-major)
        mma_gemm<64, 64, 16, false><<<dim3(1, 128, 1), 256, SM64>>>(
            x, wqT, bq, 0, q, MSROWS, DKK, DD, 0, 0, 0, 1.f);
        mma_gemm<64, 64, 16, false><<<dim3(1, 128, 1), 256, SM64>>>(
            x, wkT, bk, 0, k, MSROWS, DKK, DD, 0, 0, 0, 1.f);
        mma_gemm<64, 64, 16, false><<<dim3(1, 128, 1), 256, SM64>>>(
            x, wvT, bv, 0, v, MSROWS, DKK, DD, 0, 0, 0, 1.f);

        // scores = q @ k^T / 32  (k already [N,K] per batch)
        mma_gemm<128, 64, 32, false><<<dim3(16, 16, BB), 256, SM128>>>(
            q, k, 0, 0, scores, SS, SS, DKK,
            (long)SS * DKK, (long)SS * DKK, (long)SS * SS, inv_div);

        softmax_kernel<<<BB * SS, 256>>>(scores);

        // vT[b] = v[b]^T  (64 x 2048)
        transpose_kernel<<<dim3(2, 64, BB), tb>>>(v, vT, SS, DKK);

        // head = attn @ v
        mma_gemm<64, 64, 16, false><<<dim3(1, 16, BB), 256, SM64>>>(
            scores, vT, 0, 0, head, SS, DKK, SS,
            (long)SS * SS, (long)DKK * SS, (long)SS * DKK, 1.f);

        // y = head @ Wo_eff + bo + x
        mma_gemm<128, 64, 32, false><<<dim3(4, 128, 1), 256, SM128>>>(
            head, woT, bo, x, y, MSROWS, DD, DKK, 0, 0, 0, 1.f);

        reduce_kernel<<<RED_BLOCKS, 256>>>(y);
        finalize_kernel<<<1, 256>>>();
        normalize_kernel<<<NTOT / 256, 256>>>(y, x1);

        // h = relu(x1 @ W1 + b1)
        mma_gemm<128, 64, 32, true><<<dim3(16, 128, 1), 256, SM128>>>(
            x1, w1T, b1, 0, h, MSROWS, DFFN, DD, 0, 0, 0, 1.f);

        // y = h @ W2 + b2 + x1
        mma_gemm<128, 64, 32, false><<<dim3(4, 128, 1), 256, SM128>>>(
            h, w2T, b2, x1, y, MSROWS, DD, DFFN, 0, 0, 0, 1.f);

        reduce_kernel<<<RED_BLOCKS, 256>>>(y);
        finalize_kernel<<<1, 256>>>();
        float* dst = (it == NREP - 1) ? (float*)d_out : x;
        normalize_kernel<<<NTOT / 256, 256>>>(y, dst);
    }
}

// round 5
// speedup vs baseline: 2.1478x; 1.0990x over previous
#include <cuda_runtime.h>
#include <cuda_bf16.h>
#include <math.h>
#include <stdint.h>

// ---------------------------------------------------------------------------
// Problem dims
// ---------------------------------------------------------------------------
#define BB   8
#define SS   2048
#define DD   512
#define DKK  64
#define DFFN 2048
#define NREP 6
#define MSROWS (BB*SS)          // 16384
#define NTOT (BB*SS*DD)         // 8388608
#define RED_BLOCKS 2048

typedef __nv_bfloat16 bf16;

// ---------------------------------------------------------------------------
// Scratch (device globals; no runtime allocation allowed)
// ---------------------------------------------------------------------------
__device__ float g_x   [NTOT];
__device__ float g_x1  [NTOT];
__device__ float g_y   [NTOT];
__device__ float g_scores[(long)BB*SS*SS];   // 134 MB

__device__ bf16 g_xh [NTOT];
__device__ bf16 g_xl [NTOT];
__device__ bf16 g_x1h[NTOT];
__device__ bf16 g_x1l[NTOT];
__device__ bf16 g_qkvh[MSROWS*192];
__device__ bf16 g_qkvl[MSROWS*192];
__device__ bf16 g_vTh[BB*DKK*SS];
__device__ bf16 g_vTl[BB*DKK*SS];
__device__ bf16 g_headh[MSROWS*DKK];
__device__ bf16 g_headl[MSROWS*DKK];
__device__ bf16 g_probsh[(long)BB*SS*SS];    // 67 MB
__device__ bf16 g_probsl[(long)BB*SS*SS];    // 67 MB
__device__ bf16 g_hh[(long)MSROWS*DFFN];     // 67 MB
__device__ bf16 g_hl[(long)MSROWS*DFFN];     // 67 MB

__device__ bf16 g_wqkvTh[192*DD];
__device__ bf16 g_wqkvTl[192*DD];
__device__ bf16 g_woTh[DD*DKK];
__device__ bf16 g_woTl[DD*DKK];
__device__ bf16 g_w1Th[DFFN*DD];
__device__ bf16 g_w1Tl[DFFN*DD];
__device__ bf16 g_w2Th[DD*DFFN];
__device__ bf16 g_w2Tl[DD*DFFN];
__device__ float g_bqkv[192];

__device__ float g_psum[RED_BLOCKS];
__device__ float g_psq [RED_BLOCKS];
__device__ float g_stats[2];

// ---------------------------------------------------------------------------
// Helpers
// ---------------------------------------------------------------------------
__device__ __forceinline__ uint32_t cvta_shared_u32(const void* p) {
    uint32_t a;
    asm("{ .reg .u64 t; cvta.to.shared.u64 t, %1; cvt.u32.u64 %0, t; }" : "=r"(a) : "l"(p));
    return a;
}
__device__ __forceinline__ void cp_async16(uint32_t saddr, const void* gptr) {
    asm volatile("cp.async.cg.shared.global [%0], [%1], 16;" :: "r"(saddr), "l"(gptr));
}
__device__ __forceinline__ void cp_commit() {
    asm volatile("cp.async.commit_group;" ::: "memory");
}
template<int N>
__device__ __forceinline__ void cp_wait() {
    asm volatile("cp.async.wait_group %0;" :: "n"(N) : "memory");
}

// fp32 pair -> packed bf16x2 hi/lo (element0 in low half)
__device__ __forceinline__ void split_bf16(float e0, float e1, uint32_t& hi, uint32_t& lo) {
    asm("cvt.rn.bf16x2.f32 %0, %1, %2;" : "=r"(hi) : "f"(e1), "f"(e0));
    float h0 = __uint_as_float(hi << 16);
    float h1 = __uint_as_float(hi & 0xffff0000u);
    float l0 = e0 - h0;
    float l1 = e1 - h1;
    asm("cvt.rn.bf16x2.f32 %0, %1, %2;" : "=r"(lo) : "f"(l1), "f"(l0));
}
__device__ __forceinline__ void split1(float v, bf16& h, bf16& l) {
    h = __float2bfloat16_rn(v);
    l = __float2bfloat16_rn(v - __bfloat162float(h));
}

__device__ __forceinline__ void mma_bf16(float* c, const uint32_t* a, const uint32_t* b) {
    asm volatile(
        "mma.sync.aligned.m16n8k16.row.col.f32.bf16.bf16.f32 "
        "{%0,%1,%2,%3}, {%4,%5,%6,%7}, {%8,%9}, {%0,%1,%2,%3};"
        : "+f"(c[0]), "+f"(c[1]), "+f"(c[2]), "+f"(c[3])
        : "r"(a[0]), "r"(a[1]), "r"(a[2]), "r"(a[3]), "r"(b[0]), "r"(b[1]));
}

// ---------------------------------------------------------------------------
// Pre-split bf16 GEMM: C = alpha*(Ahi+Alo)[M,K] @ (Bhi+Blo)[N,K]^T (+bias)(+src)(ReLU)
//   3-term product: hi*hi + lo*hi + hi*lo. BM=128, BK=32, 3-stage cp.async.
//   Outputs: fp32 C (nullable) and/or bf16 hi/lo pair (nullable).
//   Smem rows: 32 bf16 used, stride 56 (=112B, 16B-aligned, conflict-free frags).
// ---------------------------------------------------------------------------
#define SMSB 56

template<int BN, int WM, int WN, bool RELU>
__global__ void __launch_bounds__(256)
mma_gemm(const bf16* __restrict__ Ahi, const bf16* __restrict__ Alo, int lda, long strideA,
         const bf16* __restrict__ Bhi, const bf16* __restrict__ Blo, int ldb, long strideB,
         const float* __restrict__ bias, const float* __restrict__ src,
         float* __restrict__ C, bf16* __restrict__ Chi, bf16* __restrict__ Clo,
         int ldc, long strideC, int K, float alpha)
{
    constexpr int MT = WM / 16;
    constexpr int NT = WN / 8;
    constexpr int WARPS_N = BN / WN;
    static_assert((128 / WM) * (BN / WN) == 8, "8 warps");

    constexpr int OFF_ALO = 128 * SMSB;
    constexpr int OFF_BHI = 256 * SMSB;
    constexpr int OFF_BLO = OFF_BHI + BN * SMSB;
    constexpr int BUFSZ   = OFF_BLO + BN * SMSB;   // elems per stage

    extern __shared__ bf16 smem[];

    const int tid  = threadIdx.x;
    const int lane = tid & 31;
    const int wid  = tid >> 5;
    const int warp_m = wid / WARPS_N;
    const int warp_n = wid % WARPS_N;
    const int qr = lane >> 2;
    const int qc = lane & 3;

    const long bz = blockIdx.z;
    Ahi += bz * strideA;  Alo += bz * strideA;
    Bhi += bz * strideB;  Blo += bz * strideB;
    if (C)   C   += bz * strideC;
    if (Chi) { Chi += bz * strideC; Clo += bz * strideC; }
    const float* srcp = src ? src + bz * strideC : (const float*)0;

    const int m0 = blockIdx.y * 128;
    const int n0 = blockIdx.x * BN;

    float acc[MT][NT][4];
#pragma unroll
    for (int i = 0; i < MT; i++)
#pragma unroll
        for (int j = 0; j < NT; j++)
#pragma unroll
            for (int u = 0; u < 4; u++) acc[i][j][u] = 0.f;

    const uint32_t sb = cvta_shared_u32(smem);

    auto load_chunk = [&](int c, int stg) {
        const int k0 = c << 5;
        const uint32_t base = sb + (uint32_t)stg * (BUFSZ * 2);
#pragma unroll
        for (int i = 0; i < 2; i++) {          // A: 128 rows x 4 chunks, hi+lo
            int idx = tid + i * 256;
            int row = idx >> 2, c8 = idx & 3;
            long g = (long)(m0 + row) * lda + k0 + c8 * 8;
            uint32_t so = (uint32_t)(row * SMSB + c8 * 8) * 2;
            cp_async16(base + so, Ahi + g);
            cp_async16(base + OFF_ALO * 2 + so, Alo + g);
        }
#pragma unroll
        for (int i = 0; i < BN / 64; i++) {    // B: BN rows x 4 chunks, hi+lo
            int idx = tid + i * 256;
            int row = idx >> 2, c8 = idx & 3;
            long g = (long)(n0 + row) * ldb + k0 + c8 * 8;
            uint32_t so = (uint32_t)(row * SMSB + c8 * 8) * 2;
            cp_async16(base + OFF_BHI * 2 + so, Bhi + g);
            cp_async16(base + OFF_BLO * 2 + so, Blo + g);
        }
    };

    const int nch = K >> 5;
    load_chunk(0, 0); cp_commit();
    load_chunk(1, 1); cp_commit();

    for (int c = 0; c < nch; c++) {
        const int stg = c % 3;
        if (c + 2 < nch) { load_chunk(c + 2, (c + 2) % 3); cp_commit(); cp_wait<2>(); }
        else             { cp_wait<0>(); }
        __syncthreads();

        const bf16* sAh = smem + stg * BUFSZ;
        const bf16* sAl = sAh + OFF_ALO;
        const bf16* sBh = smem + stg * BUFSZ + OFF_BHI;
        const bf16* sBl = smem + stg * BUFSZ + OFF_BLO;

#pragma unroll
        for (int ks = 0; ks < 2; ks++) {
            const int kk = ks * 16;
            uint32_t ah[MT][4], al[MT][4], bh[NT][2], bl[NT][2];
#pragma unroll
            for (int im = 0; im < MT; im++) {
                int r = warp_m * WM + im * 16 + qr;
                int b0 = r * SMSB + kk + 2 * qc;
                ah[im][0] = *reinterpret_cast<const uint32_t*>(&sAh[b0]);
                ah[im][1] = *reinterpret_cast<const uint32_t*>(&sAh[b0 + 8 * SMSB]);
                ah[im][2] = *reinterpret_cast<const uint32_t*>(&sAh[b0 + 8]);
                ah[im][3] = *reinterpret_cast<const uint32_t*>(&sAh[b0 + 8 * SMSB + 8]);
                al[im][0] = *reinterpret_cast<const uint32_t*>(&sAl[b0]);
                al[im][1] = *reinterpret_cast<const uint32_t*>(&sAl[b0 + 8 * SMSB]);
                al[im][2] = *reinterpret_cast<const uint32_t*>(&sAl[b0 + 8]);
                al[im][3] = *reinterpret_cast<const uint32_t*>(&sAl[b0 + 8 * SMSB + 8]);
            }
#pragma unroll
            for (int in_ = 0; in_ < NT; in_++) {
                int n = warp_n * WN + in_ * 8 + qr;
                int b0 = n * SMSB + kk + 2 * qc;
                bh[in_][0] = *reinterpret_cast<const uint32_t*>(&sBh[b0]);
                bh[in_][1] = *reinterpret_cast<const uint32_t*>(&sBh[b0 + 8]);
                bl[in_][0] = *reinterpret_cast<const uint32_t*>(&sBl[b0]);
                bl[in_][1] = *reinterpret_cast<const uint32_t*>(&sBl[b0 + 8]);
            }
#pragma unroll
            for (int im = 0; im < MT; im++)
#pragma unroll
                for (int in_ = 0; in_ < NT; in_++) {
                    mma_bf16(acc[im][in_], ah[im], bh[in_]);
                    mma_bf16(acc[im][in_], al[im], bh[in_]);
                    mma_bf16(acc[im][in_], ah[im], bl[in_]);
                }
        }
        __syncthreads();
    }

    // ---- epilogue ----
#pragma unroll
    for (int im = 0; im < MT; im++) {
#pragma unroll
        for (int in_ = 0; in_ < NT; in_++) {
            int col = n0 + warp_n * WN + in_ * 8 + qc * 2;
            float b0 = 0.f, b1 = 0.f;
            if (bias) { b0 = bias[col]; b1 = bias[col + 1]; }
#pragma unroll
            for (int h2 = 0; h2 < 2; h2++) {
                int row = m0 + warp_m * WM + im * 16 + qr + h2 * 8;
                float v0 = acc[im][in_][h2 * 2 + 0] * alpha + b0;
                float v1 = acc[im][in_][h2 * 2 + 1] * alpha + b1;
                if (srcp) {
                    float2 s2 = *reinterpret_cast<const float2*>(&srcp[(long)row * ldc + col]);
                    v0 += s2.x; v1 += s2.y;
                }
                if (RELU) { v0 = fmaxf(v0, 0.f); v1 = fmaxf(v1, 0.f); }
                if (C) {
                    float2 o; o.x = v0; o.y = v1;
                    *reinterpret_cast<float2*>(&C[(long)row * ldc + col]) = o;
                }
                if (Chi) {
                    uint32_t hp, lp;
                    split_bf16(v0, v1, hp, lp);
                    *reinterpret_cast<uint32_t*>(&Chi[(long)row * ldc + col]) = hp;
                    *reinterpret_cast<uint32_t*>(&Clo[(long)row * ldc + col]) = lp;
                }
            }
        }
    }
}

// ---------------------------------------------------------------------------
// bf16 batched transpose: out[c*R + r] = in[r*ldin + c]
// ---------------------------------------------------------------------------
__global__ void transpose_b16(const bf16* __restrict__ in, bf16* __restrict__ out,
                              int ldin, long inB, long outB, int R, int C_) {
    __shared__ bf16 tt[32][33];
    const bf16* ip = in + blockIdx.z * inB;
    bf16* op = out + blockIdx.z * outB;
    int r0 = blockIdx.y * 32, c0 = blockIdx.x * 32;
#pragma unroll
    for (int i = 0; i < 32; i += 8)
        tt[threadIdx.y + i][threadIdx.x] = ip[(long)(r0 + threadIdx.y + i) * ldin + c0 + threadIdx.x];
    __syncthreads();
#pragma unroll
    for (int i = 0; i < 32; i += 8)
        op[(long)(c0 + threadIdx.y + i) * R + r0 + threadIdx.x] = tt[threadIdx.x][threadIdx.y + i];
}

// fp32 transpose + split: outh/outl[c*R + r] = split(in[r*C_ + c])
__global__ void transpose_split_f32(const float* __restrict__ in,
                                    bf16* __restrict__ oh, bf16* __restrict__ ol,
                                    int R, int C_) {
    __shared__ float tt[32][33];
    int r0 = blockIdx.y * 32, c0 = blockIdx.x * 32;
#pragma unroll
    for (int i = 0; i < 32; i += 8)
        tt[threadIdx.y + i][threadIdx.x] = in[(long)(r0 + threadIdx.y + i) * C_ + c0 + threadIdx.x];
    __syncthreads();
#pragma unroll
    for (int i = 0; i < 32; i += 8) {
        long o = (long)(c0 + threadIdx.y + i) * R + r0 + threadIdx.x;
        bf16 h, l;
        split1(tt[threadIdx.x][threadIdx.y + i], h, l);
        oh[o] = h; ol[o] = l;
    }
}

// Combined QKV weight [192,512] K-major + bias [192]
__global__ void prep_qkvw(const float* __restrict__ Wq, const float* __restrict__ Wk,
                          const float* __restrict__ Wv, const float* __restrict__ bq,
                          const float* __restrict__ bk, const float* __restrict__ bv) {
    int idx = blockIdx.x * 256 + threadIdx.x;
    if (idx < 192 * DD) {
        int n = idx >> 9, k = idx & 511;
        const float* W = (n < 64) ? Wq : ((n < 128) ? Wk : Wv);
        float v = W[k * DKK + (n & 63)];
        split1(v, g_wqkvTh[idx], g_wqkvTl[idx]);
    }
    if (idx < 192) {
        g_bqkv[idx] = (idx < 64) ? bq[idx] : ((idx < 128) ? bk[idx - 64] : bv[idx - 128]);
    }
}

// Wo_eff^T [512,64]: woT[e][t] = sum_j Wo[(j*64+t)*512+e], split
__global__ void prep_wo(const float* __restrict__ Wo) {
    int idx = blockIdx.x * 256 + threadIdx.x;
    if (idx >= DD * DKK) return;
    int e = idx / DKK, t = idx % DKK;
    float s = 0.f;
#pragma unroll
    for (int j = 0; j < 8; j++) s += Wo[(j * DKK + t) * DD + e];
    split1(s, g_woTh[idx], g_woTl[idx]);
}

// ---------------------------------------------------------------------------
// Embedding + positional encoding; writes fp32 x and hi/lo
// ---------------------------------------------------------------------------
__global__ void embed_kernel(const int* __restrict__ ids, const float* __restrict__ emb) {
    long i2 = (long)blockIdx.x * 256 + threadIdx.x;
    if (i2 >= NTOT / 2) return;
    long e = i2 * 2;
    int d  = (int)(e & (DD - 1));
    int bs = (int)(e >> 9);
    int s  = bs & (SS - 1);
    int id = ids[bs];
    float v0 = 0.f, v1 = 0.f;
    if (id != 0) {
        const float* er = emb + (long)id * DD;
        v0 = er[d]; v1 = er[d + 1];
    }
    double f0 = pow(10000.0, (double)d / 256.0);
    double f1 = pow(10000.0, (double)(d + 1) / 256.0);
    v0 += sinf((float)((double)s / f0));
    v1 += cosf((float)((double)s / f1));
    float2 o; o.x = v0; o.y = v1;
    *reinterpret_cast<float2*>(&g_x[e]) = o;
    uint32_t hp, lp;
    split_bf16(v0, v1, hp, lp);
    *reinterpret_cast<uint32_t*>(&g_xh[e]) = hp;
    *reinterpret_cast<uint32_t*>(&g_xl[e]) = lp;
}

// ---------------------------------------------------------------------------
// Row softmax: reads fp32 scores, writes bf16 hi/lo probs. 256 thr, 8 elems each.
// ---------------------------------------------------------------------------
__global__ void softmax_kernel(const float* __restrict__ sc,
                               bf16* __restrict__ ph, bf16* __restrict__ pl) {
    long row = blockIdx.x;
    const float* p = sc + row * (long)SS;
    __shared__ float red[256];
    int t = threadIdx.x;
    float vals[8];
    float4 fA = *reinterpret_cast<const float4*>(&p[t * 8]);
    float4 fB = *reinterpret_cast<const float4*>(&p[t * 8 + 4]);
    vals[0]=fA.x; vals[1]=fA.y; vals[2]=fA.z; vals[3]=fA.w;
    vals[4]=fB.x; vals[5]=fB.y; vals[6]=fB.z; vals[7]=fB.w;
    float mx = vals[0];
#pragma unroll
    for (int j = 1; j < 8; j++) mx = fmaxf(mx, vals[j]);
    red[t] = mx; __syncthreads();
    for (int s = 128; s > 0; s >>= 1) {
        if (t < s) red[t] = fmaxf(red[t], red[t + s]);
        __syncthreads();
    }
    mx = red[0]; __syncthreads();
    float sum = 0.f;
#pragma unroll
    for (int j = 0; j < 8; j++) { vals[j] = expf(vals[j] - mx); sum += vals[j]; }
    red[t] = sum; __syncthreads();
    for (int s = 128; s > 0; s >>= 1) {
        if (t < s) red[t] += red[t + s];
        __syncthreads();
    }
    float inv = 1.0f / red[0];
    uint32_t hp[4], lp[4];
#pragma unroll
    for (int j = 0; j < 4; j++)
        split_bf16(vals[2 * j] * inv, vals[2 * j + 1] * inv, hp[j], lp[j]);
    uint4 ho; ho.x = hp[0]; ho.y = hp[1]; ho.z = hp[2]; ho.w = hp[3];
    uint4 lo; lo.x = lp[0]; lo.y = lp[1]; lo.z = lp[2]; lo.w = lp[3];
    *reinterpret_cast<uint4*>(&ph[row * (long)SS + t * 8]) = ho;
    *reinterpret_cast<uint4*>(&pl[row * (long)SS + t * 8]) = lo;
}

// ---------------------------------------------------------------------------
// Whole-tensor LayerNorm, 3 stages
// ---------------------------------------------------------------------------
__global__ void reduce_kernel(const float* __restrict__ y) {
    __shared__ float ssum[256], ssq[256];
    float a = 0.f, b = 0.f;
    for (long i = blockIdx.x * 256 + threadIdx.x; i < NTOT; i += (long)RED_BLOCKS * 256) {
        float v = y[i];
        a += v; b += v * v;
    }
    ssum[threadIdx.x] = a; ssq[threadIdx.x] = b; __syncthreads();
    for (int s = 128; s > 0; s >>= 1) {
        if (threadIdx.x < s) {
            ssum[threadIdx.x] += ssum[threadIdx.x + s];
            ssq [threadIdx.x] += ssq [threadIdx.x + s];
        }
        __syncthreads();
    }
    if (threadIdx.x == 0) { g_psum[blockIdx.x] = ssum[0]; g_psq[blockIdx.x] = ssq[0]; }
}

__global__ void finalize_kernel() {
    __shared__ double ds[256], dq[256];
    double a = 0.0, b = 0.0;
    for (int i = threadIdx.x; i < RED_BLOCKS; i += 256) {
        a += (double)g_psum[i];
        b += (double)g_psq[i];
    }
    ds[threadIdx.x] = a; dq[threadIdx.x] = b; __syncthreads();
    for (int s = 128; s > 0; s >>= 1) {
        if (threadIdx.x < s) {
            ds[threadIdx.x] += ds[threadIdx.x + s];
            dq[threadIdx.x] += dq[threadIdx.x + s];
        }
        __syncthreads();
    }
    if (threadIdx.x == 0) {
        double m = ds[0] / (double)NTOT;
        double v = dq[0] / (double)NTOT - m * m;
        g_stats[0] = (float)m;
        g_stats[1] = (float)(1.0 / sqrt(v + 1e-5));
    }
}

// normalize: fp32 out + optional bf16 hi/lo out
__global__ void normalize_kernel(const float* __restrict__ y, float* __restrict__ out,
                                 bf16* __restrict__ oh, bf16* __restrict__ ol) {
    long i2 = (long)blockIdx.x * 256 + threadIdx.x;
    long e = i2 * 2;
    if (e >= NTOT) return;
    float m = g_stats[0], rs = g_stats[1];
    float2 yy = *reinterpret_cast<const float2*>(&y[e]);
    float v0 = (yy.x - m) * rs, v1 = (yy.y - m) * rs;
    float2 o; o.x = v0; o.y = v1;
    *reinterpret_cast<float2*>(&out[e]) = o;
    if (oh) {
        uint32_t hp, lp;
        split_bf16(v0, v1, hp, lp);
        *reinterpret_cast<uint32_t*>(&oh[e]) = hp;
        *reinterpret_cast<uint32_t*>(&ol[e]) = lp;
    }
}

// ---------------------------------------------------------------------------
// Launch
// ---------------------------------------------------------------------------
extern "C" void kernel_launch(void* const* d_in, const int* in_sizes, int n_in,
                              void* d_out, int out_size)
{
    const int*   ids = (const int*)  d_in[0];
    const float* emb = (const float*)d_in[1];
    const float* Wq  = (const float*)d_in[2];
    const float* bq  = (const float*)d_in[3];
    const float* Wk  = (const float*)d_in[4];
    const float* bk  = (const float*)d_in[5];
    const float* Wv  = (const float*)d_in[6];
    const float* bv  = (const float*)d_in[7];
    const float* Wo  = (const float*)d_in[8];
    const float* bo  = (const float*)d_in[9];
    const float* W1  = (const float*)d_in[10];
    const float* b1  = (const float*)d_in[11];
    const float* W2  = (const float*)d_in[12];
    const float* b2  = (const float*)d_in[13];

    float *x, *x1, *y, *scores, *bqkv;
    bf16 *xh, *xl, *x1h, *x1l, *qkvh, *qkvl, *vTh, *vTl, *headh, *headl;
    bf16 *probsh, *probsl, *hh, *hl;
    bf16 *wqkvTh, *wqkvTl, *woTh, *woTl, *w1Th, *w1Tl, *w2Th, *w2Tl;
    cudaGetSymbolAddress((void**)&x,      g_x);
    cudaGetSymbolAddress((void**)&x1,     g_x1);
    cudaGetSymbolAddress((void**)&y,      g_y);
    cudaGetSymbolAddress((void**)&scores, g_scores);
    cudaGetSymbolAddress((void**)&xh,     g_xh);
    cudaGetSymbolAddress((void**)&xl,     g_xl);
    cudaGetSymbolAddress((void**)&x1h,    g_x1h);
    cudaGetSymbolAddress((void**)&x1l,    g_x1l);
    cudaGetSymbolAddress((void**)&qkvh,   g_qkvh);
    cudaGetSymbolAddress((void**)&qkvl,   g_qkvl);
    cudaGetSymbolAddress((void**)&vTh,    g_vTh);
    cudaGetSymbolAddress((void**)&vTl,    g_vTl);
    cudaGetSymbolAddress((void**)&headh,  g_headh);
    cudaGetSymbolAddress((void**)&headl,  g_headl);
    cudaGetSymbolAddress((void**)&probsh, g_probsh);
    cudaGetSymbolAddress((void**)&probsl, g_probsl);
    cudaGetSymbolAddress((void**)&hh,     g_hh);
    cudaGetSymbolAddress((void**)&hl,     g_hl);
    cudaGetSymbolAddress((void**)&wqkvTh, g_wqkvTh);
    cudaGetSymbolAddress((void**)&wqkvTl, g_wqkvTl);
    cudaGetSymbolAddress((void**)&woTh,   g_woTh);
    cudaGetSymbolAddress((void**)&woTl,   g_woTl);
    cudaGetSymbolAddress((void**)&w1Th,   g_w1Th);
    cudaGetSymbolAddress((void**)&w1Tl,   g_w1Tl);
    cudaGetSymbolAddress((void**)&w2Th,   g_w2Th);
    cudaGetSymbolAddress((void**)&w2Tl,   g_w2Tl);
    cudaGetSymbolAddress((void**)&bqkv,   g_bqkv);

    // dynamic smem: 3 stages * BUFSZ elems * 2B
    const int SM128 = 3 * (256 + 2 * 128) * SMSB * 2;  // 172032
    const int SM64  = 3 * (256 + 2 * 64)  * SMSB * 2;  // 129024
    cudaFuncSetAttribute((const void*)mma_gemm<128, 64, 32, false>,
                         cudaFuncAttributeMaxDynamicSharedMemorySize, SM128);
    cudaFuncSetAttribute((const void*)mma_gemm<128, 64, 32, true>,
                         cudaFuncAttributeMaxDynamicSharedMemorySize, SM128);
    cudaFuncSetAttribute((const void*)mma_gemm<64, 32, 32, false>,
                         cudaFuncAttributeMaxDynamicSharedMemorySize, SM64);

    const float inv_div = 1.0f / 32.0f;
    dim3 tb(32, 8);

    // ---- weight prep ----
    prep_qkvw<<<(192 * DD + 255) / 256, 256>>>(Wq, Wk, Wv, bq, bk, bv);
    prep_wo<<<(DD * DKK + 255) / 256, 256>>>(Wo);
    transpose_split_f32<<<dim3(DFFN / 32, DD / 32), tb>>>(W1, w1Th, w1Tl, DD, DFFN);
    transpose_split_f32<<<dim3(DD / 32, DFFN / 32), tb>>>(W2, w2Th, w2Tl, DFFN, DD);

    embed_kernel<<<NTOT / 512, 256>>>(ids, emb);

    for (int it = 0; it < NREP; it++) {
        // QKV fused: [16384,512] @ [192,512]^T -> qkv hi/lo [16384,192]
        mma_gemm<64, 32, 32, false><<<dim3(3, 128, 1), 256, SM64>>>(
            xh, xl, DD, 0, wqkvTh, wqkvTl, DD, 0, bqkv, 0,
            0, qkvh, qkvl, 192, 0, DD, 1.f);

        // scores = q @ k^T / 32 (batched; q,k are strided slices of qkv)
        mma_gemm<128, 64, 32, false><<<dim3(16, 16, BB), 256, SM128>>>(
            qkvh, qkvl, 192, (long)SS * 192,
            qkvh + 64, qkvl + 64, 192, (long)SS * 192,
            0, 0, scores, 0, 0, SS, (long)SS * SS, DKK, inv_div);

        softmax_kernel<<<BB * SS, 256>>>(scores, probsh, probsl);

        // vT = v^T per batch (bf16 hi and lo)
        transpose_b16<<<dim3(2, 64, BB), tb>>>(qkvh + 128, vTh, 192,
                                               (long)SS * 192, (long)DKK * SS, SS, DKK);
        transpose_b16<<<dim3(2, 64, BB), tb>>>(qkvl + 128, vTl, 192,
                                               (long)SS * 192, (long)DKK * SS, SS, DKK);

        // head = probs @ v  -> hi/lo [16384,64]
        mma_gemm<64, 32, 32, false><<<dim3(1, 16, BB), 256, SM64>>>(
            probsh, probsl, SS, (long)SS * SS,
            vTh, vTl, SS, (long)DKK * SS,
            0, 0, 0, headh, headl, DKK, (long)SS * DKK, SS, 1.f);

        // y = head @ Wo_eff + bo + x  (fp32)
        mma_gemm<128, 64, 32, false><<<dim3(4, 128, 1), 256, SM128>>>(
            headh, headl, DKK, 0, woTh, woTl, DKK, 0, bo, x,
            y, 0, 0, DD, 0, DKK, 1.f);

        reduce_kernel<<<RED_BLOCKS, 256>>>(y);
        finalize_kernel<<<1, 256>>>();
        normalize_kernel<<<NTOT / 512, 256>>>(y, x1, x1h, x1l);

        // h = relu(x1 @ W1 + b1) -> hi/lo only
        mma_gemm<128, 64, 32, true><<<dim3(16, 128, 1), 256, SM128>>>(
            x1h, x1l, DD, 0, w1Th, w1Tl, DD, 0, b1, 0,
            0, hh, hl, DFFN, 0, DD, 1.f);

        // y = h @ W2 + b2 + x1  (fp32)
        mma_gemm<128, 64, 32, false><<<dim3(4, 128, 1), 256, SM128>>>(
            hh, hl, DFFN, 0, w2Th, w2Tl, DFFN, 0, b2, x1,
            y, 0, 0, DD, 0, DFFN, 1.f);

        reduce_kernel<<<RED_BLOCKS, 256>>>(y);
        finalize_kernel<<<1, 256>>>();
        if (it == NREP - 1)
            normalize_kernel<<<NTOT / 512, 256>>>(y, (float*)d_out, 0, 0);
        else
            normalize_kernel<<<NTOT / 512, 256>>>(y, x, xh, xl);
    }
}

// round 6
// speedup vs baseline: 2.4825x; 1.1559x over previous
#include <cuda_runtime.h>
#include <cuda_bf16.h>
#include <math.h>
#include <stdint.h>

#define BB   8
#define SS   2048
#define DD   512
#define DKK  64
#define DFFN 2048
#define NREP 6
#define MSROWS (BB*SS)          // 16384
#define NTOT (BB*SS*DD)         // 8388608

typedef __nv_bfloat16 bf16;

// ---------------------------------------------------------------------------
// Scratch
// ---------------------------------------------------------------------------
__device__ float g_x   [NTOT];
__device__ float g_x1  [NTOT];
__device__ float g_y   [NTOT];

__device__ bf16 g_xh [NTOT];
__device__ bf16 g_xl [NTOT];
__device__ bf16 g_x1h[NTOT];
__device__ bf16 g_x1l[NTOT];
__device__ bf16 g_qkvh[MSROWS*192];
__device__ bf16 g_qkvl[MSROWS*192];
__device__ bf16 g_vTh[BB*DKK*SS];
__device__ bf16 g_vTl[BB*DKK*SS];
__device__ bf16 g_headh[MSROWS*DKK];
__device__ bf16 g_headl[MSROWS*DKK];
__device__ bf16 g_probsh[(long)BB*SS*SS];
__device__ bf16 g_probsl[(long)BB*SS*SS];
__device__ bf16 g_hh[(long)MSROWS*DFFN];
__device__ bf16 g_hl[(long)MSROWS*DFFN];

__device__ bf16 g_wqkvTh[192*DD];
__device__ bf16 g_wqkvTl[192*DD];
__device__ bf16 g_woTh[DD*DKK];
__device__ bf16 g_woTl[DD*DKK];
__device__ bf16 g_w1Th[DFFN*DD];
__device__ bf16 g_w1Tl[DFFN*DD];
__device__ bf16 g_w2Th[DD*DFFN];
__device__ bf16 g_w2Tl[DD*DFFN];
__device__ float g_bqkv[192];

__device__ float g_rpart[MSROWS*16];   // per-(row, x-tile) exp partial sums
__device__ float g_rinv [MSROWS];      // 1/rowsum
__device__ float g_psum[1024];
__device__ float g_psq [1024];
__device__ float g_stats[2];

// ---------------------------------------------------------------------------
// Helpers
// ---------------------------------------------------------------------------
__device__ __forceinline__ uint32_t cvta_shared_u32(const void* p) {
    uint32_t a;
    asm("{ .reg .u64 t; cvta.to.shared.u64 t, %1; cvt.u32.u64 %0, t; }" : "=r"(a) : "l"(p));
    return a;
}
__device__ __forceinline__ void cp_async16(uint32_t saddr, const void* gptr) {
    asm volatile("cp.async.cg.shared.global [%0], [%1], 16;" :: "r"(saddr), "l"(gptr));
}
__device__ __forceinline__ void cp_commit() {
    asm volatile("cp.async.commit_group;" ::: "memory");
}
template<int N>
__device__ __forceinline__ void cp_wait() {
    asm volatile("cp.async.wait_group %0;" :: "n"(N) : "memory");
}
__device__ __forceinline__ void ldsm_x4(uint32_t& r0, uint32_t& r1, uint32_t& r2, uint32_t& r3,
                                        uint32_t addr) {
    asm volatile("ldmatrix.sync.aligned.m8n8.x4.shared.b16 {%0,%1,%2,%3}, [%4];"
                 : "=r"(r0), "=r"(r1), "=r"(r2), "=r"(r3) : "r"(addr));
}
__device__ __forceinline__ void split_bf16(float e0, float e1, uint32_t& hi, uint32_t& lo) {
    asm("cvt.rn.bf16x2.f32 %0, %1, %2;" : "=r"(hi) : "f"(e1), "f"(e0));
    float h0 = __uint_as_float(hi << 16);
    float h1 = __uint_as_float(hi & 0xffff0000u);
    float l0 = e0 - h0;
    float l1 = e1 - h1;
    asm("cvt.rn.bf16x2.f32 %0, %1, %2;" : "=r"(lo) : "f"(l1), "f"(l0));
}
__device__ __forceinline__ void split1(float v, bf16& h, bf16& l) {
    h = __float2bfloat16_rn(v);
    l = __float2bfloat16_rn(v - __bfloat162float(h));
}
__device__ __forceinline__ void mma_bf16(float* c, const uint32_t* a, const uint32_t* b) {
    asm volatile(
        "mma.sync.aligned.m16n8k16.row.col.f32.bf16.bf16.f32 "
        "{%0,%1,%2,%3}, {%4,%5,%6,%7}, {%8,%9}, {%0,%1,%2,%3};"
        : "+f"(c[0]), "+f"(c[1]), "+f"(c[2]), "+f"(c[3])
        : "r"(a[0]), "r"(a[1]), "r"(a[2]), "r"(a[3]), "r"(b[0]), "r"(b[1]));
}

// ---------------------------------------------------------------------------
// Pre-split bf16 GEMM with mode-fused epilogues.
// MODE 0: C fp32 = acc*alpha + bias + src, + LN partials (psum/psq per CTA)
// MODE 1: Chi/Clo = split(acc*alpha + bias) [optional RELU]
// MODE 2: Chi/Clo = split(exp(acc*alpha)), row partial sums -> rpart
// MODE 3: Chi/Clo = split(acc * rinv[row])
// ---------------------------------------------------------------------------
#define SMSB 40

template<int BN, int WM, int WN, int STAGES, int MODE, bool RELU>
__global__ void __launch_bounds__(256, 2)
mma_gemm(const bf16* __restrict__ Ahi, const bf16* __restrict__ Alo, int lda, long strideA,
         const bf16* __restrict__ Bhi, const bf16* __restrict__ Blo, int ldb, long strideB,
         const float* __restrict__ bias, const float* __restrict__ src,
         float* __restrict__ C, bf16* __restrict__ Chi, bf16* __restrict__ Clo,
         int ldc, long strideC, int K, float alpha,
         float* __restrict__ rpart, const float* __restrict__ rinv,
         float* __restrict__ psum, float* __restrict__ psq)
{
    constexpr int MT = WM / 16;
    constexpr int NT = WN / 8;
    constexpr int WARPS_N = BN / WN;
    static_assert((128 / WM) * (BN / WN) == 8, "8 warps");
    static_assert(NT % 2 == 0, "NT even for ldsm pairing");

    constexpr int OFF_ALO = 128 * SMSB;
    constexpr int OFF_BHI = 256 * SMSB;
    constexpr int OFF_BLO = OFF_BHI + BN * SMSB;
    constexpr int BUFSZ   = OFF_BLO + BN * SMSB;   // bf16 elems per stage

    extern __shared__ bf16 smem[];
    __shared__ float s_red0[256];
    __shared__ float s_red1[256];
    __shared__ float s_rows[4][128];

    const int tid  = threadIdx.x;
    const int lane = tid & 31;
    const int wid  = tid >> 5;
    const int warp_m = wid / WARPS_N;
    const int warp_n = wid % WARPS_N;
    const int qr = lane >> 2;
    const int qc = lane & 3;

    const long bz = blockIdx.z;
    Ahi += bz * strideA;  Alo += bz * strideA;
    Bhi += bz * strideB;  Blo += bz * strideB;
    if (MODE == 0 && C) C += bz * strideC;
    if (Chi) { Chi += bz * strideC; Clo += bz * strideC; }
    const float* srcp = (MODE == 0 && src) ? src + bz * strideC : (const float*)0;

    const int m0 = blockIdx.y * 128;
    const int n0 = blockIdx.x * BN;

    float acc[MT][NT][4];
#pragma unroll
    for (int i = 0; i < MT; i++)
#pragma unroll
        for (int j = 0; j < NT; j++)
#pragma unroll
            for (int u = 0; u < 4; u++) acc[i][j][u] = 0.f;

    const uint32_t sb = cvta_shared_u32(smem);

    auto load_chunk = [&](int c, int stg) {
        const int k0 = c << 5;
        const uint32_t base = sb + (uint32_t)stg * (BUFSZ * 2);
#pragma unroll
        for (int i = 0; i < 2; i++) {
            int idx = tid + i * 256;
            int row = idx >> 2, c8 = idx & 3;
            long g = (long)(m0 + row) * lda + k0 + c8 * 8;
            uint32_t so = (uint32_t)(row * SMSB + c8 * 8) * 2;
            cp_async16(base + so, Ahi + g);
            cp_async16(base + OFF_ALO * 2 + so, Alo + g);
        }
#pragma unroll
        for (int i = 0; i < BN / 64; i++) {
            int idx = tid + i * 256;
            int row = idx >> 2, c8 = idx & 3;
            long g = (long)(n0 + row) * ldb + k0 + c8 * 8;
            uint32_t so = (uint32_t)(row * SMSB + c8 * 8) * 2;
            cp_async16(base + OFF_BHI * 2 + so, Bhi + g);
            cp_async16(base + OFF_BLO * 2 + so, Blo + g);
        }
    };

    const int nch = K >> 5;
#pragma unroll
    for (int s = 0; s < STAGES - 1; s++) { load_chunk(s, s); cp_commit(); }

    // ldmatrix per-lane offsets (bytes)
    const uint32_t a_off = (uint32_t)(((lane & 15) + warp_m * WM) * SMSB + (lane >> 4) * 8) * 2;
    const uint32_t b_off = (uint32_t)((((lane >> 4) & 1) * 8 + (lane & 7) + warp_n * WN) * SMSB
                                      + ((lane >> 3) & 1) * 8) * 2;

    for (int c = 0; c < nch; c++) {
        const int stg = c % STAGES;
        if (c + STAGES - 1 < nch) {
            load_chunk(c + STAGES - 1, (c + STAGES - 1) % STAGES);
            cp_commit();
            cp_wait<STAGES - 1>();
        } else {
            cp_wait<0>();
        }
        __syncthreads();

        const uint32_t stA  = sb + (uint32_t)stg * (BUFSZ * 2);
        const uint32_t stAl = stA + OFF_ALO * 2;
        const uint32_t stBh = stA + OFF_BHI * 2;
        const uint32_t stBl = stA + OFF_BLO * 2;

#pragma unroll
        for (int ks = 0; ks < 2; ks++) {
            const uint32_t kk2 = (uint32_t)ks * 32;   // 16 elems * 2B
            uint32_t bh[NT][2], bl[NT][2];
#pragma unroll
            for (int in2 = 0; in2 < NT / 2; in2++) {
                uint32_t off = b_off + (uint32_t)in2 * (16 * SMSB * 2) + kk2;
                ldsm_x4(bh[2*in2][0], bh[2*in2][1], bh[2*in2+1][0], bh[2*in2+1][1], stBh + off);
                ldsm_x4(bl[2*in2][0], bl[2*in2][1], bl[2*in2+1][0], bl[2*in2+1][1], stBl + off);
            }
#pragma unroll
            for (int im = 0; im < MT; im++) {
                uint32_t off = a_off + (uint32_t)im * (16 * SMSB * 2) + kk2;
                uint32_t ah[4], al[4];
                ldsm_x4(ah[0], ah[1], ah[2], ah[3], stA + off);
                ldsm_x4(al[0], al[1], al[2], al[3], stAl + off);
#pragma unroll
                for (int in_ = 0; in_ < NT; in_++) {
                    mma_bf16(acc[im][in_], ah, bh[in_]);
                    mma_bf16(acc[im][in_], al, bh[in_]);
                    mma_bf16(acc[im][in_], ah, bl[in_]);
                }
            }
        }
        __syncthreads();
    }

    // ---- epilogue ----
    float lsum = 0.f, lsq = 0.f;
    const float* rinvp = (MODE == 3) ? rinv + bz * SS : (const float*)0;

#pragma unroll
    for (int im = 0; im < MT; im++) {
#pragma unroll
        for (int h2 = 0; h2 < 2; h2++) {
            const int rloc = warp_m * WM + im * 16 + qr + h2 * 8;
            const int row  = m0 + rloc;
            float rs = 0.f;
            float rv = 0.f;
            if (MODE == 3) rv = rinvp[row];
#pragma unroll
            for (int in_ = 0; in_ < NT; in_++) {
                const int col = n0 + warp_n * WN + in_ * 8 + qc * 2;
                float v0 = acc[im][in_][h2 * 2 + 0] * alpha;
                float v1 = acc[im][in_][h2 * 2 + 1] * alpha;
                if (MODE == 0 || MODE == 1) {
                    if (bias) { v0 += bias[col]; v1 += bias[col + 1]; }
                }
                if (MODE == 0) {
                    if (srcp) {
                        float2 s2 = *reinterpret_cast<const float2*>(&srcp[(long)row * ldc + col]);
                        v0 += s2.x; v1 += s2.y;
                    }
                    float2 o; o.x = v0; o.y = v1;
                    *reinterpret_cast<float2*>(&C[(long)row * ldc + col]) = o;
                    lsum += v0 + v1;
                    lsq  += v0 * v0 + v1 * v1;
                } else {
                    if (MODE == 1 && RELU) { v0 = fmaxf(v0, 0.f); v1 = fmaxf(v1, 0.f); }
                    if (MODE == 2) { v0 = __expf(v0); v1 = __expf(v1); rs += v0 + v1; }
                    if (MODE == 3) { v0 *= rv; v1 *= rv; }
                    uint32_t hp, lp;
                    split_bf16(v0, v1, hp, lp);
                    *reinterpret_cast<uint32_t*>(&Chi[(long)row * ldc + col]) = hp;
                    *reinterpret_cast<uint32_t*>(&Clo[(long)row * ldc + col]) = lp;
                }
            }
            if (MODE == 2) {
                rs += __shfl_xor_sync(0xffffffffu, rs, 1);
                rs += __shfl_xor_sync(0xffffffffu, rs, 2);
                if ((lane & 3) == 0) s_rows[warp_n][rloc] = rs;
            }
        }
    }

    if (MODE == 2) {
        __syncthreads();
        if (tid < 128) {
            float s = 0.f;
#pragma unroll
            for (int wn = 0; wn < WARPS_N; wn++) s += s_rows[wn][tid];
            long rg = bz * SS + m0 + tid;
            rpart[rg * 16 + blockIdx.x] = s;
        }
    }
    if (MODE == 0) {
        s_red0[tid] = lsum; s_red1[tid] = lsq;
        __syncthreads();
        for (int s = 128; s > 0; s >>= 1) {
            if (tid < s) { s_red0[tid] += s_red0[tid + s]; s_red1[tid] += s_red1[tid + s]; }
            __syncthreads();
        }
        if (tid == 0) {
            int cta = blockIdx.y * gridDim.x + blockIdx.x;
            psum[cta] = s_red0[0];
            psq [cta] = s_red1[0];
        }
    }
}

// ---------------------------------------------------------------------------
// rowsum reciprocal: rinv[r] = 1 / sum_j rpart[r*16+j]
// ---------------------------------------------------------------------------
__global__ void rinv_kernel(const float* __restrict__ rpart, float* __restrict__ rinv) {
    int r = blockIdx.x * 256 + threadIdx.x;
    if (r >= MSROWS) return;
    float s = 0.f;
#pragma unroll
    for (int j = 0; j < 16; j++) s += rpart[r * 16 + j];
    rinv[r] = 1.0f / s;
}

// ---------------------------------------------------------------------------
// bf16 batched transpose
// ---------------------------------------------------------------------------
__global__ void transpose_b16(const bf16* __restrict__ in, bf16* __restrict__ out,
                              int ldin, long inB, long outB, int R, int C_) {
    __shared__ bf16 tt[32][33];
    const bf16* ip = in + blockIdx.z * inB;
    bf16* op = out + blockIdx.z * outB;
    int r0 = blockIdx.y * 32, c0 = blockIdx.x * 32;
#pragma unroll
    for (int i = 0; i < 32; i += 8)
        tt[threadIdx.y + i][threadIdx.x] = ip[(long)(r0 + threadIdx.y + i) * ldin + c0 + threadIdx.x];
    __syncthreads();
#pragma unroll
    for (int i = 0; i < 32; i += 8)
        op[(long)(c0 + threadIdx.y + i) * R + r0 + threadIdx.x] = tt[threadIdx.x][threadIdx.y + i];
}

__global__ void transpose_split_f32(const float* __restrict__ in,
                                    bf16* __restrict__ oh, bf16* __restrict__ ol,
                                    int R, int C_) {
    __shared__ float tt[32][33];
    int r0 = blockIdx.y * 32, c0 = blockIdx.x * 32;
#pragma unroll
    for (int i = 0; i < 32; i += 8)
        tt[threadIdx.y + i][threadIdx.x] = in[(long)(r0 + threadIdx.y + i) * C_ + c0 + threadIdx.x];
    __syncthreads();
#pragma unroll
    for (int i = 0; i < 32; i += 8) {
        long o = (long)(c0 + threadIdx.y + i) * R + r0 + threadIdx.x;
        bf16 h, l;
        split1(tt[threadIdx.x][threadIdx.y + i], h, l);
        oh[o] = h; ol[o] = l;
    }
}

__global__ void prep_qkvw(const float* __restrict__ Wq, const float* __restrict__ Wk,
                          const float* __restrict__ Wv, const float* __restrict__ bq,
                          const float* __restrict__ bk, const float* __restrict__ bv) {
    int idx = blockIdx.x * 256 + threadIdx.x;
    if (idx < 192 * DD) {
        int n = idx >> 9, k = idx & 511;
        const float* W = (n < 64) ? Wq : ((n < 128) ? Wk : Wv);
        float v = W[k * DKK + (n & 63)];
        split1(v, g_wqkvTh[idx], g_wqkvTl[idx]);
    }
    if (idx < 192) {
        g_bqkv[idx] = (idx < 64) ? bq[idx] : ((idx < 128) ? bk[idx - 64] : bv[idx - 128]);
    }
}

__global__ void prep_wo(const float* __restrict__ Wo) {
    int idx = blockIdx.x * 256 + threadIdx.x;
    if (idx >= DD * DKK) return;
    int e = idx / DKK, t = idx % DKK;
    float s = 0.f;
#pragma unroll
    for (int j = 0; j < 8; j++) s += Wo[(j * DKK + t) * DD + e];
    split1(s, g_woTh[idx], g_woTl[idx]);
}

// ---------------------------------------------------------------------------
// Embedding + positional encoding
// ---------------------------------------------------------------------------
__global__ void embed_kernel(const int* __restrict__ ids, const float* __restrict__ emb) {
    long i2 = (long)blockIdx.x * 256 + threadIdx.x;
    if (i2 >= NTOT / 2) return;
    long e = i2 * 2;
    int d  = (int)(e & (DD - 1));
    int bs = (int)(e >> 9);
    int s  = bs & (SS - 1);
    int id = ids[bs];
    float v0 = 0.f, v1 = 0.f;
    if (id != 0) {
        const float* er = emb + (long)id * DD;
        v0 = er[d]; v1 = er[d + 1];
    }
    double f0 = pow(10000.0, (double)d / 256.0);
    double f1 = pow(10000.0, (double)(d + 1) / 256.0);
    v0 += sinf((float)((double)s / f0));
    v1 += cosf((float)((double)s / f1));
    float2 o; o.x = v0; o.y = v1;
    *reinterpret_cast<float2*>(&g_x[e]) = o;
    uint32_t hp, lp;
    split_bf16(v0, v1, hp, lp);
    *reinterpret_cast<uint32_t*>(&g_xh[e]) = hp;
    *reinterpret_cast<uint32_t*>(&g_xl[e]) = lp;
}

// ---------------------------------------------------------------------------
// LayerNorm finalize + normalize
// ---------------------------------------------------------------------------
__global__ void finalize_kernel(int n) {
    __shared__ double ds[256], dq[256];
    double a = 0.0, b = 0.0;
    for (int i = threadIdx.x; i < n; i += 256) {
        a += (double)g_psum[i];
        b += (double)g_psq[i];
    }
    ds[threadIdx.x] = a; dq[threadIdx.x] = b; __syncthreads();
    for (int s = 128; s > 0; s >>= 1) {
        if (threadIdx.x < s) {
            ds[threadIdx.x] += ds[threadIdx.x + s];
            dq[threadIdx.x] += dq[threadIdx.x + s];
        }
        __syncthreads();
    }
    if (threadIdx.x == 0) {
        double m = ds[0] / (double)NTOT;
        double v = dq[0] / (double)NTOT - m * m;
        g_stats[0] = (float)m;
        g_stats[1] = (float)(1.0 / sqrt(v + 1e-5));
    }
}

__global__ void normalize_kernel(const float* __restrict__ y, float* __restrict__ out,
                                 bf16* __restrict__ oh, bf16* __restrict__ ol) {
    long i2 = (long)blockIdx.x * 256 + threadIdx.x;
    long e = i2 * 2;
    if (e >= NTOT) return;
    float m = g_stats[0], rs = g_stats[1];
    float2 yy = *reinterpret_cast<const float2*>(&y[e]);
    float v0 = (yy.x - m) * rs, v1 = (yy.y - m) * rs;
    float2 o; o.x = v0; o.y = v1;
    *reinterpret_cast<float2*>(&out[e]) = o;
    if (oh) {
        uint32_t hp, lp;
        split_bf16(v0, v1, hp, lp);
        *reinterpret_cast<uint32_t*>(&oh[e]) = hp;
        *reinterpret_cast<uint32_t*>(&ol[e]) = lp;
    }
}

// ---------------------------------------------------------------------------
// Launch
// ---------------------------------------------------------------------------
extern "C" void kernel_launch(void* const* d_in, const int* in_sizes, int n_in,
                              void* d_out, int out_size)
{
    const int*   ids = (const int*)  d_in[0];
    const float* emb = (const float*)d_in[1];
    const float* Wq  = (const float*)d_in[2];
    const float* bq  = (const float*)d_in[3];
    const float* Wk  = (const float*)d_in[4];
    const float* bk  = (const float*)d_in[5];
    const float* Wv  = (const float*)d_in[6];
    const float* bv  = (const float*)d_in[7];
    const float* Wo  = (const float*)d_in[8];
    const float* bo  = (const float*)d_in[9];
    const float* W1  = (const float*)d_in[10];
    const float* b1  = (const float*)d_in[11];
    const float* W2  = (const float*)d_in[12];
    const float* b2  = (const float*)d_in[13];

    float *x, *x1, *y, *bqkv, *rpart, *rinv, *psum, *psq;
    bf16 *xh, *xl, *x1h, *x1l, *qkvh, *qkvl, *vTh, *vTl, *headh, *headl;
    bf16 *probsh, *probsl, *hh, *hl;
    bf16 *wqkvTh, *wqkvTl, *woTh, *woTl, *w1Th, *w1Tl, *w2Th, *w2Tl;
    cudaGetSymbolAddress((void**)&x,      g_x);
    cudaGetSymbolAddress((void**)&x1,     g_x1);
    cudaGetSymbolAddress((void**)&y,      g_y);
    cudaGetSymbolAddress((void**)&xh,     g_xh);
    cudaGetSymbolAddress((void**)&xl,     g_xl);
    cudaGetSymbolAddress((void**)&x1h,    g_x1h);
    cudaGetSymbolAddress((void**)&x1l,    g_x1l);
    cudaGetSymbolAddress((void**)&qkvh,   g_qkvh);
    cudaGetSymbolAddress((void**)&qkvl,   g_qkvl);
    cudaGetSymbolAddress((void**)&vTh,    g_vTh);
    cudaGetSymbolAddress((void**)&vTl,    g_vTl);
    cudaGetSymbolAddress((void**)&headh,  g_headh);
    cudaGetSymbolAddress((void**)&headl,  g_headl);
    cudaGetSymbolAddress((void**)&probsh, g_probsh);
    cudaGetSymbolAddress((void**)&probsl, g_probsl);
    cudaGetSymbolAddress((void**)&hh,     g_hh);
    cudaGetSymbolAddress((void**)&hl,     g_hl);
    cudaGetSymbolAddress((void**)&wqkvTh, g_wqkvTh);
    cudaGetSymbolAddress((void**)&wqkvTl, g_wqkvTl);
    cudaGetSymbolAddress((void**)&woTh,   g_woTh);
    cudaGetSymbolAddress((void**)&woTl,   g_woTl);
    cudaGetSymbolAddress((void**)&w1Th,   g_w1Th);
    cudaGetSymbolAddress((void**)&w1Tl,   g_w1Tl);
    cudaGetSymbolAddress((void**)&w2Th,   g_w2Th);
    cudaGetSymbolAddress((void**)&w2Tl,   g_w2Tl);
    cudaGetSymbolAddress((void**)&bqkv,   g_bqkv);
    cudaGetSymbolAddress((void**)&rpart,  g_rpart);
    cudaGetSymbolAddress((void**)&rinv,   g_rinv);
    cudaGetSymbolAddress((void**)&psum,   g_psum);
    cudaGetSymbolAddress((void**)&psq,    g_psq);

    // dynamic smem per stage: (256 + 2*BN) * SMSB * 2 bytes
    const int SM128 = 2 * (256 + 256) * SMSB * 2;  // 81920
    const int SM64  = 3 * (256 + 128) * SMSB * 2;  // 92160

    cudaFuncSetAttribute((const void*)mma_gemm<64, 32, 32, 3, 1, false>,
                         cudaFuncAttributeMaxDynamicSharedMemorySize, SM64);
    cudaFuncSetAttribute((const void*)mma_gemm<64, 32, 32, 3, 3, false>,
                         cudaFuncAttributeMaxDynamicSharedMemorySize, SM64);
    cudaFuncSetAttribute((const void*)mma_gemm<128, 64, 32, 2, 2, false>,
                         cudaFuncAttributeMaxDynamicSharedMemorySize, SM128);
    cudaFuncSetAttribute((const void*)mma_gemm<128, 64, 32, 2, 0, false>,
                         cudaFuncAttributeMaxDynamicSharedMemorySize, SM128);
    cudaFuncSetAttribute((const void*)mma_gemm<128, 64, 32, 2, 1, true>,
                         cudaFuncAttributeMaxDynamicSharedMemorySize, SM128);

    const float inv_div = 1.0f / 32.0f;
    dim3 tb(32, 8);

    // ---- weight prep ----
    prep_qkvw<<<(192 * DD + 255) / 256, 256>>>(Wq, Wk, Wv, bq, bk, bv);
    prep_wo<<<(DD * DKK + 255) / 256, 256>>>(Wo);
    transpose_split_f32<<<dim3(DFFN / 32, DD / 32), tb>>>(W1, w1Th, w1Tl, DD, DFFN);
    transpose_split_f32<<<dim3(DD / 32, DFFN / 32), tb>>>(W2, w2Th, w2Tl, DFFN, DD);

    embed_kernel<<<NTOT / 512, 256>>>(ids, emb);

    for (int it = 0; it < NREP; it++) {
        // QKV fused: x @ wqkvT^T + bqkv -> qkv hi/lo [16384,192]
        mma_gemm<64, 32, 32, 3, 1, false><<<dim3(3, 128, 1), 256, SM64>>>(
            xh, xl, DD, 0, wqkvTh, wqkvTl, DD, 0, bqkv, 0,
            0, qkvh, qkvl, 192, 0, DD, 1.f, 0, 0, 0, 0);

        // probs(unnorm) = exp(q @ k^T / 32); row partials -> rpart
        mma_gemm<128, 64, 32, 2, 2, false><<<dim3(16, 16, BB), 256, SM128>>>(
            qkvh, qkvl, 192, (long)SS * 192,
            qkvh + 64, qkvl + 64, 192, (long)SS * 192,
            0, 0, 0, probsh, probsl, SS, (long)SS * SS, DKK, inv_div,
            rpart, 0, 0, 0);

        rinv_kernel<<<MSROWS / 256, 256>>>(rpart, rinv);

        // vT per batch (hi and lo)
        transpose_b16<<<dim3(2, 64, BB), tb>>>(qkvh + 128, vTh, 192,
                                               (long)SS * 192, (long)DKK * SS, SS, DKK);
        transpose_b16<<<dim3(2, 64, BB), tb>>>(qkvl + 128, vTl, 192,
                                               (long)SS * 192, (long)DKK * SS, SS, DKK);

        // head = (exp @ v) * rinv[row]
        mma_gemm<64, 32, 32, 3, 3, false><<<dim3(1, 16, BB), 256, SM64>>>(
            probsh, probsl, SS, (long)SS * SS,
            vTh, vTl, SS, (long)DKK * SS,
            0, 0, 0, headh, headl, DKK, (long)SS * DKK, SS, 1.f,
            0, rinv, 0, 0);

        // y = head @ Wo_eff + bo + x, with fused LN partials
        mma_gemm<128, 64, 32, 2, 0, false><<<dim3(4, 128, 1), 256, SM128>>>(
            headh, headl, DKK, 0, woTh, woTl, DKK, 0, bo, x,
            y, 0, 0, DD, 0, DKK, 1.f, 0, 0, psum, psq);

        finalize_kernel<<<1, 256>>>(512);
        normalize_kernel<<<NTOT / 512, 256>>>(y, x1, x1h, x1l);

        // h = relu(x1 @ W1 + b1) -> hi/lo
        mma_gemm<128, 64, 32, 2, 1, true><<<dim3(16, 128, 1), 256, SM128>>>(
            x1h, x1l, DD, 0, w1Th, w1Tl, DD, 0, b1, 0,
            0, hh, hl, DFFN, 0, DD, 1.f, 0, 0, 0, 0);

        // y = h @ W2 + b2 + x1, with fused LN partials
        mma_gemm<128, 64, 32, 2, 0, false><<<dim3(4, 128, 1), 256, SM128>>>(
            hh, hl, DFFN, 0, w2Th, w2Tl, DFFN, 0, b2, x1,
            y, 0, 0, DD, 0, DFFN, 1.f, 0, 0, psum, psq);

        finalize_kernel<<<1, 256>>>(512);
        if (it == NREP - 1)
            normalize_kernel<<<NTOT / 512, 256>>>(y, (float*)d_out, 0, 0);
        else
            normalize_kernel<<<NTOT / 512, 256>>>(y, x, xh, xl);
    }
}